// round 13
// baseline (speedup 1.0000x reference)
#include <cuda_runtime.h>
#include <math.h>

// ---------------------------------------------------------------------------
// SSIM (mean), 64 x 1 x 512 x 512 fp32 pairs, 11x11 Gaussian (separable).
//
// R13 (third submission of the split-field v-pass; rounds 11/12 both died in
// broker acquisition with no harness output — no kernel-level evidence):
//   - split-field v-pass: lane pairs (2l,2l+1) share one (col,group) unit;
//     even lane convolves hab, odd lane hce -> all 8 warps hot in phase A
//   - partners exchange 4 u64 via shfl_xor, each does SSIM for 4 px
//   - hce base +8 u64 pad: odd-lane word index == even+8 (mod 16) ->
//     lane-pair 16-lane phases occupy disjoint bank halves (LDS.64 clean)
//   - weights folded by symmetry (W6)
//   - R10 base: banded rings, templated ring slots, div-free staging,
//     single fused kernel with atomic-ticket deterministic reduction
// ---------------------------------------------------------------------------

#define IMGW 512
#define IMGH 512
#define NIMG 64
#define TW 64
#define TH 16
#define RAD 5
#define IWD (TW + 2*RAD)          // 74
#define ISTR 75
#define SRING 16
#define HRING 32
#define HST 33
#define HPAD 8                    // hce pad (u64): (2112+8) mod 16 == 8
#define NTHREADS 256
#define TILES_X (IMGW / TW)       // 8
#define YCH 4
#define CHROWS (IMGH / YCH)       // 128
#define NBANDS (CHROWS / TH)      // 8
#define NBLOCKS (NIMG * TILES_X * YCH)   // 2048

typedef unsigned long long u64;

__device__ float g_partials[NBLOCKS];
__device__ unsigned int g_ticket;

__device__ __forceinline__ u64 pk(float lo, float hi) {
    u64 r; asm("mov.b64 %0, {%1, %2};" : "=l"(r) : "f"(lo), "f"(hi)); return r;
}
__device__ __forceinline__ void upk(u64 v, float& lo, float& hi) {
    asm("mov.b64 {%0, %1}, %2;" : "=f"(lo), "=f"(hi) : "l"(v));
}
__device__ __forceinline__ u64 f2fma(u64 a, u64 b, u64 c) {
    u64 d; asm("fma.rn.f32x2 %0, %1, %2, %3;" : "=l"(d) : "l"(a), "l"(b), "l"(c)); return d;
}
__device__ __forceinline__ u64 f2mul(u64 a, u64 b) {
    u64 d; asm("mul.rn.f32x2 %0, %1, %2;" : "=l"(d) : "l"(a), "l"(b)); return d;
}

// weight index fold: tap d in [0,10] -> W6[min(d, 10-d)]
#define WIX(d) ((d) < 6 ? (d) : 10 - (d))

// Division-free stage of `nrows` rows [g0, g0+nrows) into the sxy ring.
// r = tid>>4 (up to 16 rows), c0 = tid&15, 5 unrolled column steps (>= IWD).
__device__ __forceinline__ void stageN(u64* __restrict__ sxy,
                                       const float* __restrict__ p1,
                                       const float* __restrict__ p2,
                                       int bx0, int g0, int nrows, int tid) {
    const int r  = tid >> 4;
    const int c0 = tid & 15;
    if (r >= nrows) return;
    const int gy = g0 + r;
    const bool rowok = (unsigned)gy < (unsigned)IMGH;
    const float* q1 = p1 + gy * IMGW;
    const float* q2 = p2 + gy * IMGW;
    const int base = (gy & (SRING - 1)) * ISTR;
#pragma unroll
    for (int k = 0; k < 5; k++) {
        const int c = c0 + (k << 4);
        if (c < IWD) {
            const int gx = bx0 + c;
            float x = 0.f, y = 0.f;
            if (rowok && (unsigned)gx < (unsigned)IMGW) {
                x = __ldg(q1 + gx);
                y = __ldg(q2 + gx);
            }
            sxy[base + c] = pk(x, y);
        }
    }
}

// Rolling 4-wide h strip: row grow, output cols cb..cb+3, transposed write.
__device__ __forceinline__ void hstrip4(const u64* __restrict__ sxy,
                                        u64* __restrict__ hab,
                                        u64* __restrict__ hce,
                                        int grow, int cb,
                                        const u64* __restrict__ W6) {
    const int slot = grow & (HRING - 1);
    const int ib = (grow & (SRING - 1)) * ISTR + cb;
    const int ob = cb * HST + slot;
    u64 aab[4], ace[4];
#pragma unroll
    for (int j = 0; j < 14; j++) {
        u64 cur = sxy[ib + j];
        float x, y; upk(cur, x, y);
        u64 tr = pk(fmaf(x, x, y * y), x * y);
        const int klo = (j - 10) > 0 ? (j - 10) : 0;
        const int khi = j < 3 ? j : 3;
#pragma unroll
        for (int k = klo; k <= khi; k++) {
            if (k == j) { aab[k] = f2mul(W6[0], cur); ace[k] = f2mul(W6[0], tr); }
            else        { aab[k] = f2fma(W6[WIX(j - k)], cur, aab[k]);
                          ace[k] = f2fma(W6[WIX(j - k)], tr,  ace[k]); }
        }
    }
#pragma unroll
    for (int k = 0; k < 4; k++) {
        hab[ob + k * HST] = aab[k];
        hce[ob + k * HST] = ace[k];
    }
}

// Half v-pass: one array column, 8 output rows accumulated; partner lane
// (xor 1) holds the other array's accumulators. Exchange 4 u64 via shfl;
// each lane computes SSIM for 4 px. S0 = compile-time start slot so every
// LDS gets an immediate offset.
template<int S0>
__device__ __forceinline__ float vhalf8(const u64* __restrict__ col,
                                        const u64* __restrict__ W6,
                                        int odd) {
    u64 acc[8];
#pragma unroll
    for (int j = 0; j < 18; j++) {
        const int slot = (S0 + j) & (HRING - 1);   // compile-time constant
        u64 v = col[slot];
        const int klo = (j - 10) > 0 ? (j - 10) : 0;
        const int khi = j < 7 ? j : 7;
#pragma unroll
        for (int k = klo; k <= khi; k++) {
            if (k == j) acc[k] = f2mul(W6[0], v);
            else        acc[k] = f2fma(W6[WIX(j - k)], v, acc[k]);
        }
    }
    const float C1 = 0.0001f;
    const float C2 = 0.0009f;
    float sum = 0.f;
#pragma unroll
    for (int t = 0; t < 4; t++) {
        u64 sendv = odd ? acc[t] : acc[t + 4];
        u64 got = __shfl_xor_sync(0xffffffffu, sendv, 1);
        u64 mab = odd ? got : acc[t];          // mu pair
        u64 mce = odd ? acc[t + 4] : got;      // (x^2+y^2, x*y) pair
        float mu1, mu2, cc, ce;
        upk(mab, mu1, mu2);
        upk(mce, cc, ce);
        float m11 = mu1 * mu1;
        float m22 = mu2 * mu2;
        float m12 = mu1 * mu2;
        float s12  = ce - m12;
        float ssum = cc - m11 - m22;
        float num = fmaf(2.f, m12, C1) * fmaf(2.f, s12, C2);
        float den = (m11 + m22 + C1) * (ssum + C2);
        sum += __fdividef(num, den);
    }
    return sum;
}

__global__ __launch_bounds__(NTHREADS, 4)
void ssim_fused_kernel(const float* __restrict__ img1,
                       const float* __restrict__ img2,
                       const float* __restrict__ win,
                       float* __restrict__ out) {
    extern __shared__ u64 sm8[];
    u64* sxy = sm8;                          // SRING*ISTR = 1200
    u64* hab = sxy + SRING * ISTR;           // TW*HST = 2112 (column-major)
    u64* hce = hab + TW * HST + HPAD;        // +8 u64: disjoint bank halves
    float* gw  = (float*)(hce + TW * HST);   // 11 (+pad)
    float* red = gw + 12;                    // 8
    __shared__ int s_isLast;

    const int tid = threadIdx.x;

    if (tid < 11) {
        float g5 = sqrtf(win[5 * 11 + 5]);
        gw[tid] = win[5 * 11 + tid] / g5;
    }

    const int imgoff = blockIdx.z * (IMGW * IMGH);
    const float* p1 = img1 + imgoff;
    const float* p2 = img2 + imgoff;
    const int bx0 = blockIdx.x * TW - RAD;
    const int Y0  = blockIdx.y * CHROWS;

    // ---- Prologue part 1: rows [Y0-5, Y0+11) ------------------------------
    stageN(sxy, p1, p2, bx0, Y0 - RAD, 16, tid);
    __syncthreads();

    const float w0s = gw[0], w1s = gw[1], w2s = gw[2],
                w3s = gw[3], w4s = gw[4], w5s = gw[5];
    const u64 W6[6] = { pk(w0s, w0s), pk(w1s, w1s), pk(w2s, w2s),
                        pk(w3s, w3s), pk(w4s, w4s), pk(w5s, w5s) };

    // h-filter those 16 rows: one strip per thread
    {
        int r  = tid & 15;
        int cb = (tid >> 4) << 2;
        hstrip4(sxy, hab, hce, Y0 - RAD + r, cb, W6);
    }
    __syncthreads();

    // ---- Prologue part 2: rows [Y0+11, Y0+21) -----------------------------
    stageN(sxy, p1, p2, bx0, Y0 + 11, 10, tid);
    __syncthreads();
    if (tid < 160) {
        int r  = tid >> 4;            // 0..9
        int cb = (tid & 15) << 2;
        hstrip4(sxy, hab, hce, Y0 + 11 + r, cb, W6);
    }
    __syncthreads();

    // ---- Band loop --------------------------------------------------------
    // unit u = warp*16 + (lane>>1) in [0,128): col = u&63, group g = u>>6
    // even lane of pair: hab half; odd lane: hce half.
    const int lane = tid & 31;
    const int wrp  = tid >> 5;
    const int u    = wrp * 16 + (lane >> 1);
    const int odd  = lane & 1;
    const int ccol = u & 63;
    const int grp  = u >> 6;                  // warps 0-3 -> 0, 4-7 -> 1
    const u64* vcol = (odd ? hce : hab) + ccol * HST;

    float sum = 0.f;

    for (int b = 0; b < NBANDS; b++) {
        const int B = Y0 + b * TH;

        // Phase A: split-field v-pass (all 8 warps), then stage band b+1.
        // Start slot s0 = (B + 8g - 5) & 31, with B%32 = 16*(b&1):
        //   b even: g0 -> 27, g1 -> 3 ; b odd: g0 -> 11, g1 -> 19
        if ((b & 1) == 0)
            sum += grp ? vhalf8<3>(vcol, W6, odd)  : vhalf8<27>(vcol, W6, odd);
        else
            sum += grp ? vhalf8<19>(vcol, W6, odd) : vhalf8<11>(vcol, W6, odd);

        if (b + 1 < NBANDS)
            stageN(sxy, p1, p2, bx0, B + TH + RAD, TH, tid);
        __syncthreads();

        // Phase B: h-pass rows [B+21, B+37) (16 rows x 16 strips)
        if (b + 1 < NBANDS) {
            int r  = tid & 15;
            int cb = (tid >> 4) << 2;
            hstrip4(sxy, hab, hce, B + TH + RAD + r, cb, W6);
            __syncthreads();
        }
    }

    // ---- Block reduction --------------------------------------------------
#pragma unroll
    for (int o = 16; o; o >>= 1)
        sum += __shfl_down_sync(0xffffffffu, sum, o);
    if ((tid & 31) == 0) red[tid >> 5] = sum;
    __syncthreads();

    const int bi = (blockIdx.z * gridDim.y + blockIdx.y) * gridDim.x + blockIdx.x;
    if (tid == 0) {
        float t = 0.f;
#pragma unroll
        for (int w = 0; w < NTHREADS / 32; w++) t += red[w];
        g_partials[bi] = t;
        __threadfence();
        unsigned int tk = atomicAdd(&g_ticket, 1u);
        s_isLast = (tk == NBLOCKS - 1);
    }
    __syncthreads();

    // ---- Last CTA: deterministic final reduction --------------------------
    if (s_isLast) {
        float s = 0.f;
        for (int i = tid; i < NBLOCKS; i += NTHREADS)
            s += g_partials[i];
        __syncthreads();
#pragma unroll
        for (int o = 16; o; o >>= 1)
            s += __shfl_down_sync(0xffffffffu, s, o);
        if ((tid & 31) == 0) red[tid >> 5] = s;
        __syncthreads();
        if (tid == 0) {
            float t = 0.f;
#pragma unroll
            for (int w = 0; w < NTHREADS / 32; w++) t += red[w];
            out[0] = t * (1.0f / (float)((long long)NIMG * IMGW * IMGH));
            g_ticket = 0;
        }
    }
}

extern "C" void kernel_launch(void* const* d_in, const int* in_sizes, int n_in,
                              void* d_out, int out_size) {
    const float* img1 = (const float*)d_in[0];
    const float* img2 = (const float*)d_in[1];
    const float* win  = (const float*)d_in[2];

    const size_t SMEM = (size_t)(SRING * ISTR + 2 * TW * HST + HPAD) * sizeof(u64)
                      + 20 * sizeof(float);
    cudaFuncSetAttribute(ssim_fused_kernel,
                         cudaFuncAttributeMaxDynamicSharedMemorySize, (int)SMEM);

    dim3 grid(TILES_X, YCH, NIMG);
    ssim_fused_kernel<<<grid, NTHREADS, SMEM>>>(img1, img2, win, (float*)d_out);
}

// round 16
// speedup vs baseline: 1.0577x; 1.0577x over previous
#include <cuda_runtime.h>
#include <math.h>

// ---------------------------------------------------------------------------
// SSIM (mean), 64 x 1 x 512 x 512 fp32 pairs, 11x11 Gaussian (separable).
//
// R16 (third submission of the interleaved-h variant; rounds 14 and 15 both
// died in broker acquisition with no harness output — no kernel evidence):
// R10 base (best passing: 104.7us) + interleaved h-array, 128-bit smem ops.
//   - hab/hce fused into ulonglong2 hx[col*33+slot] (16B-aligned base):
//     v-pass 36->18 LDS.128 per thread, h-pass 8->4 STS.128 per strip,
//     bank-conflict-free in both access patterns (verified byte/4 mod 32)
//   - W6 symmetry fold for register headroom
//   - rest identical to R10: banded rings, templated ring slots {27,3,11,19},
//     div-free staging, single fused kernel + atomic-ticket reduction
//   - R13's split-field experiment stays reverted (measured regression)
// ---------------------------------------------------------------------------

#define IMGW 512
#define IMGH 512
#define NIMG 64
#define TW 64
#define TH 16
#define RAD 5
#define IWD (TW + 2*RAD)          // 74
#define ISTR 75
#define SRING 16
#define HRING 32
#define HST 33
#define NTHREADS 256
#define TILES_X (IMGW / TW)       // 8
#define YCH 4
#define CHROWS (IMGH / YCH)       // 128
#define NBANDS (CHROWS / TH)      // 8
#define NBLOCKS (NIMG * TILES_X * YCH)   // 2048

typedef unsigned long long u64;

__device__ float g_partials[NBLOCKS];
__device__ unsigned int g_ticket;

__device__ __forceinline__ u64 pk(float lo, float hi) {
    u64 r; asm("mov.b64 %0, {%1, %2};" : "=l"(r) : "f"(lo), "f"(hi)); return r;
}
__device__ __forceinline__ void upk(u64 v, float& lo, float& hi) {
    asm("mov.b64 {%0, %1}, %2;" : "=f"(lo), "=f"(hi) : "l"(v));
}
__device__ __forceinline__ u64 f2fma(u64 a, u64 b, u64 c) {
    u64 d; asm("fma.rn.f32x2 %0, %1, %2, %3;" : "=l"(d) : "l"(a), "l"(b), "l"(c)); return d;
}
__device__ __forceinline__ u64 f2mul(u64 a, u64 b) {
    u64 d; asm("mul.rn.f32x2 %0, %1, %2;" : "=l"(d) : "l"(a), "l"(b)); return d;
}

// weight index fold: tap d in [0,10] -> W6[min(d, 10-d)]
#define WIX(d) ((d) < 6 ? (d) : 10 - (d))

// Division-free stage of `nrows` rows [g0, g0+nrows) into the sxy ring.
// r = tid>>4 (up to 16 rows), c0 = tid&15, 5 unrolled column steps (>= IWD).
__device__ __forceinline__ void stageN(u64* __restrict__ sxy,
                                       const float* __restrict__ p1,
                                       const float* __restrict__ p2,
                                       int bx0, int g0, int nrows, int tid) {
    const int r  = tid >> 4;
    const int c0 = tid & 15;
    if (r >= nrows) return;
    const int gy = g0 + r;
    const bool rowok = (unsigned)gy < (unsigned)IMGH;
    const float* q1 = p1 + gy * IMGW;
    const float* q2 = p2 + gy * IMGW;
    const int base = (gy & (SRING - 1)) * ISTR;
#pragma unroll
    for (int k = 0; k < 5; k++) {
        const int c = c0 + (k << 4);
        if (c < IWD) {
            const int gx = bx0 + c;
            float x = 0.f, y = 0.f;
            if (rowok && (unsigned)gx < (unsigned)IMGW) {
                x = __ldg(q1 + gx);
                y = __ldg(q2 + gx);
            }
            sxy[base + c] = pk(x, y);
        }
    }
}

// Rolling 4-wide h strip: row grow, output cols cb..cb+3; writes interleaved
// (hab,hce) pairs with a single STS.128 per output column.
__device__ __forceinline__ void hstrip4(const u64* __restrict__ sxy,
                                        ulonglong2* __restrict__ hx,
                                        int grow, int cb,
                                        const u64* __restrict__ W6) {
    const int slot = grow & (HRING - 1);
    const int ib = (grow & (SRING - 1)) * ISTR + cb;
    const int ob = cb * HST + slot;
    u64 aab[4], ace[4];
#pragma unroll
    for (int j = 0; j < 14; j++) {
        u64 cur = sxy[ib + j];
        float x, y; upk(cur, x, y);
        u64 tr = pk(fmaf(x, x, y * y), x * y);
        const int klo = (j - 10) > 0 ? (j - 10) : 0;
        const int khi = j < 3 ? j : 3;
#pragma unroll
        for (int k = klo; k <= khi; k++) {
            if (k == j) { aab[k] = f2mul(W6[0], cur); ace[k] = f2mul(W6[0], tr); }
            else        { aab[k] = f2fma(W6[WIX(j - k)], cur, aab[k]);
                          ace[k] = f2fma(W6[WIX(j - k)], tr,  ace[k]); }
        }
    }
#pragma unroll
    for (int k = 0; k < 4; k++)
        hx[ob + k * HST] = make_ulonglong2(aab[k], ace[k]);
}

// V-pass + SSIM for one column, 8 output rows; both fields from one LDS.128.
// S0 = compile-time start slot -> every load has an immediate offset.
template<int S0>
__device__ __forceinline__ float vssim8x(const ulonglong2* __restrict__ colp,
                                         const u64* __restrict__ W6) {
    u64 aab[8], ace[8];
#pragma unroll
    for (int j = 0; j < 18; j++) {
        const int slot = (S0 + j) & (HRING - 1);   // compile-time constant
        ulonglong2 v = colp[slot];
        const int klo = (j - 10) > 0 ? (j - 10) : 0;
        const int khi = j < 7 ? j : 7;
#pragma unroll
        for (int k = klo; k <= khi; k++) {
            if (k == j) { aab[k] = f2mul(W6[0], v.x); ace[k] = f2mul(W6[0], v.y); }
            else        { aab[k] = f2fma(W6[WIX(j - k)], v.x, aab[k]);
                          ace[k] = f2fma(W6[WIX(j - k)], v.y, ace[k]); }
        }
    }
    const float C1 = 0.0001f;
    const float C2 = 0.0009f;
    float sum = 0.f;
#pragma unroll
    for (int k = 0; k < 8; k++) {
        float mu1, mu2, cc, ce;
        upk(aab[k], mu1, mu2);
        upk(ace[k], cc, ce);
        float m11 = mu1 * mu1;
        float m22 = mu2 * mu2;
        float m12 = mu1 * mu2;
        float s12  = ce - m12;
        float ssum = cc - m11 - m22;
        float num = fmaf(2.f, m12, C1) * fmaf(2.f, s12, C2);
        float den = (m11 + m22 + C1) * (ssum + C2);
        sum += __fdividef(num, den);
    }
    return sum;
}

__global__ __launch_bounds__(NTHREADS, 4)
void ssim_fused_kernel(const float* __restrict__ img1,
                       const float* __restrict__ img2,
                       const float* __restrict__ win,
                       float* __restrict__ out) {
    extern __shared__ u64 sm8[];
    u64* sxy = sm8;                              // SRING*ISTR = 1200 u64
    ulonglong2* hx = (ulonglong2*)(sxy + SRING * ISTR);  // byte 9600: 16B aligned
    float* gw  = (float*)((u64*)hx + 2 * TW * HST);      // 11 (+pad)
    float* red = gw + 12;                        // 8
    __shared__ int s_isLast;

    const int tid = threadIdx.x;

    if (tid < 11) {
        float g5 = sqrtf(win[5 * 11 + 5]);
        gw[tid] = win[5 * 11 + tid] / g5;
    }

    const int imgoff = blockIdx.z * (IMGW * IMGH);
    const float* p1 = img1 + imgoff;
    const float* p2 = img2 + imgoff;
    const int bx0 = blockIdx.x * TW - RAD;
    const int Y0  = blockIdx.y * CHROWS;

    // ---- Prologue part 1: stage rows [Y0-5, Y0+11) ------------------------
    stageN(sxy, p1, p2, bx0, Y0 - RAD, 16, tid);
    __syncthreads();

    const float w0s = gw[0], w1s = gw[1], w2s = gw[2],
                w3s = gw[3], w4s = gw[4], w5s = gw[5];
    const u64 W6[6] = { pk(w0s, w0s), pk(w1s, w1s), pk(w2s, w2s),
                        pk(w3s, w3s), pk(w4s, w4s), pk(w5s, w5s) };

    // h-filter those 16 rows: one 4-wide strip per thread (16 rows x 16 strips)
    {
        int r  = tid & 15;
        int cb = (tid >> 4) << 2;
        hstrip4(sxy, hx, Y0 - RAD + r, cb, W6);
    }
    __syncthreads();

    // ---- Prologue part 2: stage rows [Y0+11, Y0+21), h-filter -------------
    stageN(sxy, p1, p2, bx0, Y0 + 11, 10, tid);
    __syncthreads();
    if (tid < 160) {
        int r  = tid >> 4;            // 0..9
        int cb = (tid & 15) << 2;
        hstrip4(sxy, hx, Y0 + 11 + r, cb, W6);
    }
    __syncthreads();

    // ---- Band loop --------------------------------------------------------
    float sum = 0.f;

    for (int b = 0; b < NBANDS; b++) {
        const int B = Y0 + b * TH;

        // Phase A: v-pass (tid<128), then stage band b+1 (all threads).
        // Start slot s0 = (B + 8g - 5) & 31, B%32 = 16*(b&1):
        //   b even: g0 -> 27, g1 -> 3 ; b odd: g0 -> 11, g1 -> 19
        if (tid < 128) {
            const int c = tid & 63;
            const int g = tid >> 6;
            const ulonglong2* colp = hx + c * HST;
            if ((b & 1) == 0)
                sum += g ? vssim8x<3>(colp, W6)  : vssim8x<27>(colp, W6);
            else
                sum += g ? vssim8x<19>(colp, W6) : vssim8x<11>(colp, W6);
        }
        if (b + 1 < NBANDS)
            stageN(sxy, p1, p2, bx0, B + TH + RAD, TH, tid);
        __syncthreads();

        // Phase B: h-pass rows [B+21, B+37) (16 rows x 16 strips)
        if (b + 1 < NBANDS) {
            int r  = tid & 15;
            int cb = (tid >> 4) << 2;
            hstrip4(sxy, hx, B + TH + RAD + r, cb, W6);
            __syncthreads();
        }
    }

    // ---- Block reduction --------------------------------------------------
#pragma unroll
    for (int o = 16; o; o >>= 1)
        sum += __shfl_down_sync(0xffffffffu, sum, o);
    if ((tid & 31) == 0) red[tid >> 5] = sum;
    __syncthreads();

    const int bi = (blockIdx.z * gridDim.y + blockIdx.y) * gridDim.x + blockIdx.x;
    if (tid == 0) {
        float t = 0.f;
#pragma unroll
        for (int w = 0; w < NTHREADS / 32; w++) t += red[w];
        g_partials[bi] = t;
        __threadfence();
        unsigned int tk = atomicAdd(&g_ticket, 1u);
        s_isLast = (tk == NBLOCKS - 1);
    }
    __syncthreads();

    // ---- Last CTA: deterministic final reduction --------------------------
    if (s_isLast) {
        float s = 0.f;
        for (int i = tid; i < NBLOCKS; i += NTHREADS)
            s += g_partials[i];
        __syncthreads();
#pragma unroll
        for (int o = 16; o; o >>= 1)
            s += __shfl_down_sync(0xffffffffu, s, o);
        if ((tid & 31) == 0) red[tid >> 5] = s;
        __syncthreads();
        if (tid == 0) {
            float t = 0.f;
#pragma unroll
            for (int w = 0; w < NTHREADS / 32; w++) t += red[w];
            out[0] = t * (1.0f / (float)((long long)NIMG * IMGW * IMGH));
            g_ticket = 0;
        }
    }
}

extern "C" void kernel_launch(void* const* d_in, const int* in_sizes, int n_in,
                              void* d_out, int out_size) {
    const float* img1 = (const float*)d_in[0];
    const float* img2 = (const float*)d_in[1];
    const float* win  = (const float*)d_in[2];

    const size_t SMEM = (size_t)(SRING * ISTR + 2 * TW * HST) * sizeof(u64)
                      + 20 * sizeof(float);
    cudaFuncSetAttribute(ssim_fused_kernel,
                         cudaFuncAttributeMaxDynamicSharedMemorySize, (int)SMEM);

    dim3 grid(TILES_X, YCH, NIMG);
    ssim_fused_kernel<<<grid, NTHREADS, SMEM>>>(img1, img2, win, (float*)d_out);
}